// round 12
// baseline (speedup 1.0000x reference)
#include <cuda_runtime.h>
#include <cuda_fp16.h>
#include <cstdint>

#define TT 1024
#define HH 50
#define PP 16
#define RH 72    // ring row stride in halfs (144B)
#define NPR 21   // weight pairs kept in registers (pairs 0..20); pairs 21..24 in smem

__device__ __forceinline__ float tanh_hw(float v) {
    float r; asm("tanh.approx.f32 %0, %1;" : "=f"(r) : "f"(v)); return r;
}
__device__ __forceinline__ unsigned h2u(__half2 h) { return *reinterpret_cast<unsigned*>(&h); }
__device__ __forceinline__ __half2 u2h(unsigned u) { return *reinterpret_cast<__half2*>(&u); }
__device__ __forceinline__ __half2 tanh_h2(__half2 v) {
    unsigned r; asm("tanh.approx.f16x2 %0, %1;" : "=r"(r) : "r"(h2u(v))); return u2h(r);
}
__device__ __forceinline__ unsigned prmt(unsigned a, unsigned b, unsigned sel) {
    unsigned d; asm("prmt.b32 %0, %1, %2, %3;" : "=r"(d) : "r"(a), "r"(b), "r"(sel)); return d;
}
__device__ __forceinline__ void bar_pair(int id) {
    asm volatile("bar.sync %0, %1;" :: "r"(id), "r"(64) : "memory");
}
__device__ __forceinline__ void cp_async16(uint32_t dst, const void* src) {
    asm volatile("cp.async.ca.shared.global [%0], [%1], 16;" :: "r"(dst), "l"(src) : "memory");
}

// one batch's 4 gate dots + packed activation tail
__device__ __forceinline__ void gates_eval(
    const __half* __restrict__ hrow,
    const __half2 (&w)[4][NPR],
    const __half2* __restrict__ wsc,          // &wsm[0][u], row stride 64 half2
    __half2 xx, __half2 wx_if, __half2 wb_if, __half2 wx_go, __half2 wb_go,
    __half2& v_if, __half2& v_go)
{
    const uint4* rp = reinterpret_cast<const uint4*>(hrow);
    const unsigned htail = reinterpret_cast<const unsigned*>(hrow)[24];  // h48,h49
    __half2 a0[4], a1[4];
    #pragma unroll
    for (int k = 0; k < 4; ++k) { a0[k] = __floats2half2_rn(0.f, 0.f); a1[k] = a0[k]; }
    #pragma unroll
    for (int q = 0; q < 5; ++q) {                   // pairs 0..19 (units 0..39), reg weights
        uint4 hv = rp[q];
        #pragma unroll
        for (int k = 0; k < 4; ++k) {
            a0[k] = __hfma2(w[k][4 * q + 0], u2h(hv.x), a0[k]);
            a1[k] = __hfma2(w[k][4 * q + 1], u2h(hv.y), a1[k]);
            a0[k] = __hfma2(w[k][4 * q + 2], u2h(hv.z), a0[k]);
            a1[k] = __hfma2(w[k][4 * q + 3], u2h(hv.w), a1[k]);
        }
    }
    {                                               // pairs 20..24: pair20 reg, 21..24 smem
        uint4 hv = rp[5];
        #pragma unroll
        for (int k = 0; k < 4; ++k) {
            a0[k] = __hfma2(w[k][20],           u2h(hv.x),  a0[k]);
            a1[k] = __hfma2(wsc[(k * 4 + 0) * 64], u2h(hv.y),  a1[k]);
            a0[k] = __hfma2(wsc[(k * 4 + 1) * 64], u2h(hv.z),  a0[k]);
            a1[k] = __hfma2(wsc[(k * 4 + 2) * 64], u2h(hv.w),  a1[k]);
            a0[k] = __hfma2(wsc[(k * 4 + 3) * 64], u2h(htail), a0[k]);
        }
    }
    const __half2 si = __hadd2(a0[0], a1[0]);
    const __half2 sf = __hadd2(a0[1], a1[1]);
    const __half2 sg = __hadd2(a0[2], a1[2]);
    const __half2 so = __hadd2(a0[3], a1[3]);
    const __half2 xg_if = __hfma2(xx, wx_if, wb_if);
    const __half2 xg_go = __hfma2(xx, wx_go, wb_go);
    const __half2 raw_if = __hadd2(
        __hadd2(u2h(prmt(h2u(si), h2u(sf), 0x5410)),
                u2h(prmt(h2u(si), h2u(sf), 0x7632))), xg_if);
    const __half2 raw_go = __hadd2(
        __hadd2(u2h(prmt(h2u(sg), h2u(so), 0x5410)),
                u2h(prmt(h2u(sg), h2u(so), 0x7632))), xg_go);
    const __half2 H55   = __floats2half2_rn(0.5f, 0.5f);
    const __half2 Hm_go = __floats2half2_rn(1.0f, 0.5f);
    const __half2 Ha_go = __floats2half2_rn(0.0f, 0.5f);
    v_if = __hfma2(tanh_h2(raw_if), H55, H55);      // (sig_i, sig_f)
    v_go = __hfma2(tanh_h2(raw_go), Hm_go, Ha_go);  // (tanh_g, sig_o)
}

__global__ __launch_bounds__(128, 4)
void lstm_fused_kernel(const float* __restrict__ x,
                       const float* __restrict__ params,
                       const float* __restrict__ W_ih,
                       const float* __restrict__ W_hh,
                       const float* __restrict__ b_ih,
                       const float* __restrict__ b_hh,
                       const float* __restrict__ W_lin,
                       const float* __restrict__ b_lin,
                       float* __restrict__ out)
{
    __shared__ __align__(16) __half2 xsh[4][TT];       // (x,x) per batch
    __shared__ __align__(16) __half  ring[4][32][RH];  // per-batch fp16 h ring
    __shared__ __align__(16) float   psm[4][32][20];   // params window (padded stride)
    __shared__ __align__(16) float   wlin[68];
    __shared__ __align__(16) __half2 wsm[16][64];      // weight pairs 21..24 x 4 gates

    const int tid  = threadIdx.x;                      // 0..127
    const int dom  = tid >> 6;                         // domain (0/1), 2 batches each
    const int u    = tid & 63;                         // unit index (>=50 pads)
    const int wd   = (tid >> 5) & 1;                   // warp within domain
    const int lane = tid & 31;
    const int jj   = min(u, HH - 1);
    const int b0cta = blockIdx.x * 4;
    const int bA = dom * 2, bB = dom * 2 + 1;          // CTA-local batch slots
    const int barid = dom + 1;

    // ---- init ----
    for (int i = tid; i < 4 * TT; i += 128) {
        const int p = i >> 10, ti = i & (TT - 1);
        xsh[p][ti] = __half2half2(__float2half_rn(x[(size_t)(b0cta + p) * TT + ti]));
    }
    for (int i = tid; i < 4 * HH; i += 128)
        ring[i / HH][31][i % HH] = __float2half_rn(0.0f);
    if (tid < 68) wlin[tid] = (tid < HH + PP) ? W_lin[tid] : 0.0f;
    if (tid < 64) {
        const int jq = min(tid, HH - 1);
        #pragma unroll
        for (int k = 0; k < 4; ++k) {
            const float sc = (k == 2) ? 1.0f : 0.5f;
            const float* wr = W_hh + (k * HH + jq) * HH;
            #pragma unroll
            for (int p = 0; p < 4; ++p) {
                const int pr = NPR + p;               // pairs 21..24
                wsm[k * 4 + p][tid] =
                    __floats2half2_rn(sc * wr[2 * pr], sc * wr[2 * pr + 1]);
            }
        }
    }
    const float blin = b_lin[0];

    // ---- per-thread reg weights: pairs 0..20 for gates i,f,g,o (0.5 folded in i,f,o) ----
    __half2 w[4][NPR];
    __half2 wx_if, wb_if, wx_go, wb_go;
    {
        float wihv[4], biasv[4];
        #pragma unroll
        for (int k = 0; k < 4; ++k) {
            const int r = k * HH + jj;
            const float sc = (k == 2) ? 1.0f : 0.5f;
            wihv[k]  = sc * W_ih[r];
            biasv[k] = sc * (b_ih[r] + b_hh[r]);
            const float2* wr = reinterpret_cast<const float2*>(W_hh + r * HH);
            #pragma unroll
            for (int q = 0; q < NPR; ++q) {
                float2 v = wr[q];
                w[k][q] = __floats2half2_rn(sc * v.x, sc * v.y);
            }
        }
        wx_if = __floats2half2_rn(wihv[0], wihv[1]);
        wb_if = __floats2half2_rn(biasv[0], biasv[1]);
        wx_go = __floats2half2_rn(wihv[2], wihv[3]);
        wb_go = __floats2half2_rn(biasv[2], biasv[3]);
    }
    __syncthreads();

    const __half2* wsc = &wsm[0][u];
    float cA = 0.0f, cB = 0.0f;

    #pragma unroll 1
    for (int t = 0; t < TT; ++t) {
        const int cur  = t & 31;
        const int prev = (t + 31) & 31;

        // ---- params prefetch for [t, t+31], both of this domain's batches ----
        if ((t & 31) == 0) {
            #pragma unroll
            for (int i = 0; i < 4; ++i) {
                const int cc   = u + 64 * i;           // 0..255
                const int bsel = cc >> 7;
                const int slot = (cc >> 2) & 31;
                const int seg  = cc & 3;
                const float* src = params +
                    ((size_t)(b0cta + dom * 2 + bsel) * TT + (t + slot)) * PP + seg * 4;
                const uint32_t dst = (uint32_t)__cvta_generic_to_shared(
                    &psm[dom * 2 + bsel][slot][seg * 4]);
                cp_async16(dst, src);
            }
            asm volatile("cp.async.commit_group;" ::: "memory");
        }

        // ---- batch A: dot + tail ----
        {
            __half2 vif, vgo;
            gates_eval(&ring[bA][prev][0], w, wsc, xsh[bA][t],
                       wx_if, wb_if, wx_go, wb_go, vif, vgo);
            const __half2 m = __hmul2(vif, vgo);
            const float ig = __low2float(m);
            const float vf = __high2float(vif);
            const float vo = __high2float(vgo);
            cA = fmaf(vf, cA, ig);
            const float h = vo * tanh_hw(cA);
            if (u < HH) ring[bA][cur][u] = __float2half_rn(h);
        }

        // ---- batch B: dot + tail (hides A's tail latency under B's dot issue) ----
        {
            __half2 vif, vgo;
            gates_eval(&ring[bB][prev][0], w, wsc, xsh[bB][t],
                       wx_if, wb_if, wx_go, wb_go, vif, vgo);
            const __half2 m = __hmul2(vif, vgo);
            const float ig = __low2float(m);
            const float vf = __high2float(vif);
            const float vo = __high2float(vgo);
            cB = fmaf(vf, cB, ig);
            const float h = vo * tanh_hw(cB);
            if (u < HH) ring[bB][cur][u] = __float2half_rn(h);
        }

        if ((t & 31) == 31) {
            asm volatile("cp.async.wait_group 0;" ::: "memory");
            bar_pair(barid);                           // h + psm visible in domain

            // ---- flush: warp wd handles batch (dom*2+wd), 1 lane per timestep ----
            {
                const int bl = dom * 2 + wd;
                const int tg = t - 31 + lane;
                const __half* hr = ring[bl][lane];
                float s = blin;
                #pragma unroll
                for (int q = 0; q < 6; ++q) {
                    uint4 v = reinterpret_cast<const uint4*>(hr)[q];
                    float2 f0 = __half22float2(u2h(v.x));
                    float2 f1 = __half22float2(u2h(v.y));
                    float2 f2 = __half22float2(u2h(v.z));
                    float2 f3 = __half22float2(u2h(v.w));
                    s = fmaf(f0.x, wlin[8*q+0], s); s = fmaf(f0.y, wlin[8*q+1], s);
                    s = fmaf(f1.x, wlin[8*q+2], s); s = fmaf(f1.y, wlin[8*q+3], s);
                    s = fmaf(f2.x, wlin[8*q+4], s); s = fmaf(f2.y, wlin[8*q+5], s);
                    s = fmaf(f3.x, wlin[8*q+6], s); s = fmaf(f3.y, wlin[8*q+7], s);
                }
                {
                    float2 ft = __half22float2(u2h(reinterpret_cast<const unsigned*>(hr)[24]));
                    s = fmaf(ft.x, wlin[48], s); s = fmaf(ft.y, wlin[49], s);
                }
                const float4* p4 = reinterpret_cast<const float4*>(&psm[bl][lane][0]);
                #pragma unroll
                for (int q = 0; q < 4; ++q) {
                    float4 p = p4[q];
                    s = fmaf(p.x, wlin[HH + 4*q + 0], s);
                    s = fmaf(p.y, wlin[HH + 4*q + 1], s);
                    s = fmaf(p.z, wlin[HH + 4*q + 2], s);
                    s = fmaf(p.w, wlin[HH + 4*q + 3], s);
                }
                out[(size_t)(b0cta + bl) * TT + tg] = s;
            }
            bar_pair(barid);                           // flush done before ring reuse
        } else {
            bar_pair(barid);                           // h[cur] visible within domain
        }
    }
}

extern "C" void kernel_launch(void* const* d_in, const int* in_sizes, int n_in,
                              void* d_out, int out_size)
{
    const float* x      = (const float*)d_in[0];
    const float* params = (const float*)d_in[1];
    const float* W_ih   = (const float*)d_in[2];
    const float* W_hh   = (const float*)d_in[3];
    const float* b_ih   = (const float*)d_in[4];
    const float* b_hh   = (const float*)d_in[5];
    const float* W_lin  = (const float*)d_in[6];
    const float* b_lin  = (const float*)d_in[7];
    float* out = (float*)d_out;

    const int B = in_sizes[0] / TT;                    // 1024
    lstm_fused_kernel<<<B / 4, 128>>>(x, params, W_ih, W_hh, b_ih, b_hh,
                                      W_lin, b_lin, out);
}

// round 13
// speedup vs baseline: 1.2924x; 1.2924x over previous
#include <cuda_runtime.h>
#include <cuda_fp16.h>
#include <cstdint>

#define TT 1024
#define HH 50
#define PP 16
#define RH 72    // ring row stride in halfs (144B)

__device__ __forceinline__ float tanh_hw(float v) {
    float r; asm("tanh.approx.f32 %0, %1;" : "=f"(r) : "f"(v)); return r;
}
__device__ __forceinline__ unsigned h2u(__half2 h) { return *reinterpret_cast<unsigned*>(&h); }
__device__ __forceinline__ __half2 u2h(unsigned u) { return *reinterpret_cast<__half2*>(&u); }
__device__ __forceinline__ __half2 tanh_h2(__half2 v) {
    unsigned r; asm("tanh.approx.f16x2 %0, %1;" : "=r"(r) : "r"(h2u(v))); return u2h(r);
}
__device__ __forceinline__ unsigned prmt(unsigned a, unsigned b, unsigned sel) {
    unsigned d; asm("prmt.b32 %0, %1, %2, %3;" : "=r"(d) : "r"(a), "r"(b), "r"(sel)); return d;
}
__device__ __forceinline__ void cp_async16(uint32_t dst, const void* src) {
    asm volatile("cp.async.ca.shared.global [%0], [%1], 16;" :: "r"(dst), "l"(src) : "memory");
}

__global__ __launch_bounds__(224, 2)
void lstm_fused_kernel(const float* __restrict__ x,
                       const float* __restrict__ params,
                       const float* __restrict__ W_ih,
                       const float* __restrict__ W_hh,
                       const float* __restrict__ b_ih,
                       const float* __restrict__ b_hh,
                       const float* __restrict__ W_lin,
                       const float* __restrict__ b_lin,
                       float* __restrict__ out)
{
    __shared__ __align__(16) __half2 xsh[4][TT];       // (x,x) per batch
    __shared__ __align__(16) __half  ring[4][32][RH];  // per-batch fp16 h ring
    __shared__ __align__(16) float   psm[4][32][20];   // params window (padded stride)
    __shared__ __align__(16) float   wlin[68];

    const int tid = threadIdx.x;                       // 0..223
    // unit-slot packing: 200 real slots over 224 lanes; slot s -> (batch s/50, unit s%50)
    const int s  = min(tid, 199);
    const int q  = s / HH;                             // CTA-local batch 0..3
    const int u  = s - q * HH;                         // unit 0..49
    const bool real_slot = (tid < 200);
    const int b0cta = blockIdx.x * 4;

    // ---- init ----
    for (int i = tid; i < 4 * TT; i += 224) {
        const int p = i >> 10, ti = i & (TT - 1);
        xsh[p][ti] = __half2half2(__float2half_rn(x[(size_t)(b0cta + p) * TT + ti]));
    }
    for (int i = tid; i < 4 * HH; i += 224)
        ring[i / HH][31][i % HH] = __float2half_rn(0.0f);
    if (tid < 68) wlin[tid] = (tid < HH + PP) ? W_lin[tid] : 0.0f;
    const float blin = b_lin[0];

    // ---- per-thread weights: gates i,f,g,o for (q,u); 0.5 folded into i,f,o ----
    __half2 w[4][25];
    __half2 wx_if, wb_if, wx_go, wb_go;
    {
        float wihv[4], biasv[4];
        #pragma unroll
        for (int k = 0; k < 4; ++k) {
            const int r = k * HH + u;
            const float sc = (k == 2) ? 1.0f : 0.5f;
            wihv[k]  = sc * W_ih[r];
            biasv[k] = sc * (b_ih[r] + b_hh[r]);
            const float2* wr = reinterpret_cast<const float2*>(W_hh + r * HH);
            #pragma unroll
            for (int p = 0; p < 25; ++p) {
                float2 v = wr[p];
                w[k][p] = __floats2half2_rn(sc * v.x, sc * v.y);
            }
        }
        wx_if = __floats2half2_rn(wihv[0], wihv[1]);
        wb_if = __floats2half2_rn(biasv[0], biasv[1]);
        wx_go = __floats2half2_rn(wihv[2], wihv[3]);
        wb_go = __floats2half2_rn(biasv[2], biasv[3]);
    }
    const __half2 H55   = __floats2half2_rn(0.5f, 0.5f);
    const __half2 Hm_go = __floats2half2_rn(1.0f, 0.5f);
    const __half2 Ha_go = __floats2half2_rn(0.0f, 0.5f);
    __syncthreads();

    float c = 0.0f;

    #pragma unroll 1
    for (int t = 0; t < TT; ++t) {
        const int cur  = t & 31;
        const int prev = (t + 31) & 31;

        // ---- params prefetch for window [t, t+31], all 4 batches ----
        if ((t & 31) == 0) {
            for (int i = tid; i < 512; i += 224) {     // 4 batches x 32 slots x 4 segs
                const int bsel = i >> 7;
                const int slot = (i >> 2) & 31;
                const int seg  = i & 3;
                const float* src = params +
                    ((size_t)(b0cta + bsel) * TT + (t + slot)) * PP + seg * 4;
                const uint32_t dst = (uint32_t)__cvta_generic_to_shared(
                    &psm[bsel][slot][seg * 4]);
                cp_async16(dst, src);
            }
            asm volatile("cp.async.commit_group;" ::: "memory");
        }

        // ---- h[t-1]: 6 LDS.128 + 1 LDS.32 (<=2 addr groups in mixed warps) ----
        const __half* hrow = &ring[q][prev][0];
        uint4 hv[6];
        const uint4* rp = reinterpret_cast<const uint4*>(hrow);
        #pragma unroll
        for (int p = 0; p < 6; ++p) hv[p] = rp[p];
        const unsigned htail = reinterpret_cast<const unsigned*>(hrow)[24];  // h48,h49

        // ---- 4 gate dots ----
        __half2 a0[4], a1[4];
        #pragma unroll
        for (int k = 0; k < 4; ++k) { a0[k] = __floats2half2_rn(0.f, 0.f); a1[k] = a0[k]; }
        #pragma unroll
        for (int p = 0; p < 6; ++p) {
            #pragma unroll
            for (int k = 0; k < 4; ++k) {
                a0[k] = __hfma2(w[k][4 * p + 0], u2h(hv[p].x), a0[k]);
                a1[k] = __hfma2(w[k][4 * p + 1], u2h(hv[p].y), a1[k]);
                a0[k] = __hfma2(w[k][4 * p + 2], u2h(hv[p].z), a0[k]);
                a1[k] = __hfma2(w[k][4 * p + 3], u2h(hv[p].w), a1[k]);
            }
        }
        #pragma unroll
        for (int k = 0; k < 4; ++k) a0[k] = __hfma2(w[k][24], u2h(htail), a0[k]);

        const __half2 si = __hadd2(a0[0], a1[0]);
        const __half2 sf = __hadd2(a0[1], a1[1]);
        const __half2 sg = __hadd2(a0[2], a1[2]);
        const __half2 so = __hadd2(a0[3], a1[3]);

        // ---- packed tail ----
        const __half2 xx = xsh[q][t];
        const __half2 xg_if = __hfma2(xx, wx_if, wb_if);
        const __half2 xg_go = __hfma2(xx, wx_go, wb_go);
        const __half2 raw_if = __hadd2(
            __hadd2(u2h(prmt(h2u(si), h2u(sf), 0x5410)),
                    u2h(prmt(h2u(si), h2u(sf), 0x7632))), xg_if);
        const __half2 raw_go = __hadd2(
            __hadd2(u2h(prmt(h2u(sg), h2u(so), 0x5410)),
                    u2h(prmt(h2u(sg), h2u(so), 0x7632))), xg_go);

        const __half2 v_if = __hfma2(tanh_h2(raw_if), H55, H55);      // (sig_i, sig_f)
        const __half2 v_go = __hfma2(tanh_h2(raw_go), Hm_go, Ha_go);  // (tanh_g, sig_o)

        const __half2 m = __hmul2(v_if, v_go);         // lo = i*g
        const float ig = __low2float(m);
        const float vf = __high2float(v_if);
        const float vo = __high2float(v_go);

        c = fmaf(vf, c, ig);
        const float h = vo * tanh_hw(c);
        if (real_slot) ring[q][cur][u] = __float2half_rn(h);

        if ((t & 31) == 31) {
            asm volatile("cp.async.wait_group 0;" ::: "memory");
            __syncthreads();                           // h + psm visible

            // ---- flush: 1 thread per (batch, timestep), threads 0..127 ----
            if (tid < 128) {
                const int fb   = tid >> 5;
                const int slot = tid & 31;
                const int tg   = t - 31 + slot;
                const __half* hr = ring[fb][slot];
                float sacc = blin;
                #pragma unroll
                for (int p = 0; p < 6; ++p) {
                    uint4 v = reinterpret_cast<const uint4*>(hr)[p];
                    float2 f0 = __half22float2(u2h(v.x));
                    float2 f1 = __half22float2(u2h(v.y));
                    float2 f2 = __half22float2(u2h(v.z));
                    float2 f3 = __half22float2(u2h(v.w));
                    sacc = fmaf(f0.x, wlin[8*p+0], sacc); sacc = fmaf(f0.y, wlin[8*p+1], sacc);
                    sacc = fmaf(f1.x, wlin[8*p+2], sacc); sacc = fmaf(f1.y, wlin[8*p+3], sacc);
                    sacc = fmaf(f2.x, wlin[8*p+4], sacc); sacc = fmaf(f2.y, wlin[8*p+5], sacc);
                    sacc = fmaf(f3.x, wlin[8*p+6], sacc); sacc = fmaf(f3.y, wlin[8*p+7], sacc);
                }
                {
                    float2 ft = __half22float2(u2h(reinterpret_cast<const unsigned*>(hr)[24]));
                    sacc = fmaf(ft.x, wlin[48], sacc); sacc = fmaf(ft.y, wlin[49], sacc);
                }
                const float4* p4 = reinterpret_cast<const float4*>(&psm[fb][slot][0]);
                #pragma unroll
                for (int p = 0; p < 4; ++p) {
                    float4 pv = p4[p];
                    sacc = fmaf(pv.x, wlin[HH + 4*p + 0], sacc);
                    sacc = fmaf(pv.y, wlin[HH + 4*p + 1], sacc);
                    sacc = fmaf(pv.z, wlin[HH + 4*p + 2], sacc);
                    sacc = fmaf(pv.w, wlin[HH + 4*p + 3], sacc);
                }
                out[(size_t)(b0cta + fb) * TT + tg] = sacc;
            }
            __syncthreads();                           // flush done before ring reuse
        } else {
            __syncthreads();                           // h[cur] visible
        }
    }
}

extern "C" void kernel_launch(void* const* d_in, const int* in_sizes, int n_in,
                              void* d_out, int out_size)
{
    const float* x      = (const float*)d_in[0];
    const float* params = (const float*)d_in[1];
    const float* W_ih   = (const float*)d_in[2];
    const float* W_hh   = (const float*)d_in[3];
    const float* b_ih   = (const float*)d_in[4];
    const float* b_hh   = (const float*)d_in[5];
    const float* W_lin  = (const float*)d_in[6];
    const float* b_lin  = (const float*)d_in[7];
    float* out = (float*)d_out;

    const int B = in_sizes[0] / TT;                    // 1024
    lstm_fused_kernel<<<B / 4, 224>>>(x, params, W_ih, W_hh, b_ih, b_hh,
                                      W_lin, b_lin, out);
}

// round 16
// speedup vs baseline: 1.3737x; 1.0629x over previous
#include <cuda_runtime.h>
#include <cuda_fp16.h>
#include <cstdint>

#define TT 1024
#define HH 50
#define PP 16
#define RH 72    // ring row stride in halfs (144B)

__device__ __forceinline__ float tanh_hw(float v) {
    float r; asm("tanh.approx.f32 %0, %1;" : "=f"(r) : "f"(v)); return r;
}
__device__ __forceinline__ unsigned h2u(__half2 h) { return *reinterpret_cast<unsigned*>(&h); }
__device__ __forceinline__ __half2 u2h(unsigned u) { return *reinterpret_cast<__half2*>(&u); }
__device__ __forceinline__ __half2 tanh_h2(__half2 v) {
    unsigned r; asm("tanh.approx.f16x2 %0, %1;" : "=r"(r) : "r"(h2u(v))); return u2h(r);
}
__device__ __forceinline__ unsigned prmt(unsigned a, unsigned b, unsigned sel) {
    unsigned d; asm("prmt.b32 %0, %1, %2, %3;" : "=r"(d) : "r"(a), "r"(b), "r"(sel)); return d;
}
__device__ __forceinline__ void cp_async16(uint32_t dst, const void* src) {
    asm volatile("cp.async.ca.shared.global [%0], [%1], 16;" :: "r"(dst), "l"(src) : "memory");
}

__global__ __launch_bounds__(224, 2)
void lstm_fused_kernel(const float* __restrict__ x,
                       const float* __restrict__ params,
                       const float* __restrict__ W_ih,
                       const float* __restrict__ W_hh,
                       const float* __restrict__ b_ih,
                       const float* __restrict__ b_hh,
                       const float* __restrict__ W_lin,
                       const float* __restrict__ b_lin,
                       float* __restrict__ out)
{
    __shared__ __align__(16) __half2 xsh[4][TT];       // (x,x) per batch
    __shared__ __align__(16) __half  ring[4][32][RH];  // per-batch fp16 h ring
    __shared__ __align__(16) float   psm[4][32][20];   // params window (padded stride)
    __shared__ __align__(16) float   wlin[68];

    const int tid = threadIdx.x;                       // 0..223
    // unit-slot packing: 200 real slots over 224 lanes; slot s -> (batch s/50, unit s%50)
    const int s  = min(tid, 199);
    const int q  = s / HH;                             // CTA-local batch 0..3
    const int u  = s - q * HH;                         // unit 0..49
    const bool real_slot = (tid < 200);
    const int b0cta = blockIdx.x * 4;

    // ---- init ----
    for (int i = tid; i < 4 * TT; i += 224) {
        const int p = i >> 10, ti = i & (TT - 1);
        xsh[p][ti] = __half2half2(__float2half_rn(x[(size_t)(b0cta + p) * TT + ti]));
    }
    for (int i = tid; i < 4 * HH; i += 224)
        ring[i / HH][31][i % HH] = __float2half_rn(0.0f);
    if (tid < 68) wlin[tid] = (tid < HH + PP) ? W_lin[tid] : 0.0f;
    const float blin = b_lin[0];

    // ---- per-thread weights: gates i,f,g,o for (q,u); 0.5 folded into i,f,o ----
    __half2 w[4][25];
    __half2 wx_if, wb_if, wx_go, wb_go;
    {
        float wihv[4], biasv[4];
        #pragma unroll
        for (int k = 0; k < 4; ++k) {
            const int r = k * HH + u;
            const float sc = (k == 2) ? 1.0f : 0.5f;
            wihv[k]  = sc * W_ih[r];
            biasv[k] = sc * (b_ih[r] + b_hh[r]);
            const float2* wr = reinterpret_cast<const float2*>(W_hh + r * HH);
            #pragma unroll
            for (int p = 0; p < 25; ++p) {
                float2 v = wr[p];
                w[k][p] = __floats2half2_rn(sc * v.x, sc * v.y);
            }
        }
        wx_if = __floats2half2_rn(wihv[0], wihv[1]);
        wb_if = __floats2half2_rn(biasv[0], biasv[1]);
        wx_go = __floats2half2_rn(wihv[2], wihv[3]);
        wb_go = __floats2half2_rn(biasv[2], biasv[3]);
    }
    const __half2 H55   = __floats2half2_rn(0.5f, 0.5f);
    const __half2 Hm_go = __floats2half2_rn(1.0f, 0.5f);
    const __half2 Ha_go = __floats2half2_rn(0.0f, 0.5f);
    __syncthreads();

    const __half*  ringq = &ring[q][0][0];
    const __half2* xq    = &xsh[q][0];
    float c = 0.0f;

    #pragma unroll 1
    for (int win = 0; win < TT / 32; ++win) {
        const int t0 = win * 32;

        // ---- params prefetch for window [t0, t0+31], all 4 batches ----
        for (int i = tid; i < 512; i += 224) {         // 4 batches x 32 slots x 4 segs
            const int bsel = i >> 7;
            const int slot = (i >> 2) & 31;
            const int seg  = i & 3;
            const float* src = params +
                ((size_t)(b0cta + bsel) * TT + (t0 + slot)) * PP + seg * 4;
            const uint32_t dst = (uint32_t)__cvta_generic_to_shared(
                &psm[bsel][slot][seg * 4]);
            cp_async16(dst, src);
        }
        asm volatile("cp.async.commit_group;" ::: "memory");

        // ---- 32 recurrence steps; no branch tests inside ----
        #pragma unroll 4
        for (int tw = 0; tw < 32; ++tw) {
            const int prev = (tw + 31) & 31;

            // h[t-1]: 6 LDS.128 + 1 LDS.32 broadcast
            const __half* hrow = ringq + prev * RH;
            uint4 hv[6];
            const uint4* rp = reinterpret_cast<const uint4*>(hrow);
            #pragma unroll
            for (int p = 0; p < 6; ++p) hv[p] = rp[p];
            const unsigned htail = reinterpret_cast<const unsigned*>(hrow)[24];

            // 4 gate dots
            __half2 a0[4], a1[4];
            #pragma unroll
            for (int k = 0; k < 4; ++k) { a0[k] = __floats2half2_rn(0.f, 0.f); a1[k] = a0[k]; }
            #pragma unroll
            for (int p = 0; p < 6; ++p) {
                #pragma unroll
                for (int k = 0; k < 4; ++k) {
                    a0[k] = __hfma2(w[k][4 * p + 0], u2h(hv[p].x), a0[k]);
                    a1[k] = __hfma2(w[k][4 * p + 1], u2h(hv[p].y), a1[k]);
                    a0[k] = __hfma2(w[k][4 * p + 2], u2h(hv[p].z), a0[k]);
                    a1[k] = __hfma2(w[k][4 * p + 3], u2h(hv[p].w), a1[k]);
                }
            }
            #pragma unroll
            for (int k = 0; k < 4; ++k) a0[k] = __hfma2(w[k][24], u2h(htail), a0[k]);

            const __half2 si = __hadd2(a0[0], a1[0]);
            const __half2 sf = __hadd2(a0[1], a1[1]);
            const __half2 sg = __hadd2(a0[2], a1[2]);
            const __half2 so = __hadd2(a0[3], a1[3]);

            // packed tail
            const __half2 xx = xq[t0 + tw];
            const __half2 xg_if = __hfma2(xx, wx_if, wb_if);
            const __half2 xg_go = __hfma2(xx, wx_go, wb_go);
            const __half2 raw_if = __hadd2(
                __hadd2(u2h(prmt(h2u(si), h2u(sf), 0x5410)),
                        u2h(prmt(h2u(si), h2u(sf), 0x7632))), xg_if);
            const __half2 raw_go = __hadd2(
                __hadd2(u2h(prmt(h2u(sg), h2u(so), 0x5410)),
                        u2h(prmt(h2u(sg), h2u(so), 0x7632))), xg_go);

            const __half2 v_if = __hfma2(tanh_h2(raw_if), H55, H55);      // (sig_i, sig_f)
            const __half2 v_go = __hfma2(tanh_h2(raw_go), Hm_go, Ha_go);  // (tanh_g, sig_o)

            const __half2 m = __hmul2(v_if, v_go);     // lo = i*g
            const float ig = __low2float(m);
            const float vf = __high2float(v_if);
            const float vo = __high2float(v_go);

            c = fmaf(vf, c, ig);
            const float h = vo * tanh_hw(c);
            if (real_slot) ring[q][tw][u] = __float2half_rn(h);

            __syncthreads();                           // h[cur] visible
        }

        // ---- window flush: 1 thread per (batch, timestep) ----
        asm volatile("cp.async.wait_group 0;" ::: "memory");
        __syncthreads();                               // psm visible to all threads
        if (tid < 128) {
            const int fb   = tid >> 5;
            const int slot = tid & 31;
            const int tg   = t0 + slot;
            const __half* hr = ring[fb][slot];
            float sacc = blin;
            #pragma unroll
            for (int p = 0; p < 6; ++p) {
                uint4 v = reinterpret_cast<const uint4*>(hr)[p];
                float2 f0 = __half22float2(u2h(v.x));
                float2 f1 = __half22float2(u2h(v.y));
                float2 f2 = __half22float2(u2h(v.z));
                float2 f3 = __half22float2(u2h(v.w));
                sacc = fmaf(f0.x, wlin[8*p+0], sacc); sacc = fmaf(f0.y, wlin[8*p+1], sacc);
                sacc = fmaf(f1.x, wlin[8*p+2], sacc); sacc = fmaf(f1.y, wlin[8*p+3], sacc);
                sacc = fmaf(f2.x, wlin[8*p+4], sacc); sacc = fmaf(f2.y, wlin[8*p+5], sacc);
                sacc = fmaf(f3.x, wlin[8*p+6], sacc); sacc = fmaf(f3.y, wlin[8*p+7], sacc);
            }
            {
                float2 ft = __half22float2(u2h(reinterpret_cast<const unsigned*>(hr)[24]));
                sacc = fmaf(ft.x, wlin[48], sacc); sacc = fmaf(ft.y, wlin[49], sacc);
            }
            const float4* p4 = reinterpret_cast<const float4*>(&psm[fb][slot][0]);
            #pragma unroll
            for (int p = 0; p < 4; ++p) {
                float4 pv = p4[p];
                sacc = fmaf(pv.x, wlin[HH + 4*p + 0], sacc);
                sacc = fmaf(pv.y, wlin[HH + 4*p + 1], sacc);
                sacc = fmaf(pv.z, wlin[HH + 4*p + 2], sacc);
                sacc = fmaf(pv.w, wlin[HH + 4*p + 3], sacc);
            }
            out[(size_t)(b0cta + fb) * TT + tg] = sacc;
        }
        __syncthreads();                               // flush done before ring reuse
    }
}

extern "C" void kernel_launch(void* const* d_in, const int* in_sizes, int n_in,
                              void* d_out, int out_size)
{
    const float* x      = (const float*)d_in[0];
    const float* params = (const float*)d_in[1];
    const float* W_ih   = (const float*)d_in[2];
    const float* W_hh   = (const float*)d_in[3];
    const float* b_ih   = (const float*)d_in[4];
    const float* b_hh   = (const float*)d_in[5];
    const float* W_lin  = (const float*)d_in[6];
    const float* b_lin  = (const float*)d_in[7];
    float* out = (float*)d_out;

    const int B = in_sizes[0] / TT;                    // 1024
    lstm_fused_kernel<<<B / 4, 224>>>(x, params, W_ih, W_hh, b_ih, b_hh,
                                      W_lin, b_lin, out);
}

// round 17
// speedup vs baseline: 1.7683x; 1.2873x over previous
#include <cuda_runtime.h>
#include <cuda_fp16.h>
#include <cstdint>

#define TT 1024
#define HH 50
#define PP 16
#define NB 7     // batches per CTA (grid 147 -> exactly 1 CTA per SM)
#define NT 352   // threads (NB*50 = 350 real slots)
#define RH 56    // ring row stride in halfs (112B, 16B-aligned)

__device__ __forceinline__ float tanh_hw(float v) {
    float r; asm("tanh.approx.f32 %0, %1;" : "=f"(r) : "f"(v)); return r;
}
__device__ __forceinline__ unsigned h2u(__half2 h) { return *reinterpret_cast<unsigned*>(&h); }
__device__ __forceinline__ __half2 u2h(unsigned u) { return *reinterpret_cast<__half2*>(&u); }
__device__ __forceinline__ __half2 tanh_h2(__half2 v) {
    unsigned r; asm("tanh.approx.f16x2 %0, %1;" : "=r"(r) : "r"(h2u(v))); return u2h(r);
}
__device__ __forceinline__ unsigned prmt(unsigned a, unsigned b, unsigned sel) {
    unsigned d; asm("prmt.b32 %0, %1, %2, %3;" : "=r"(d) : "r"(a), "r"(b), "r"(sel)); return d;
}
__device__ __forceinline__ void cp_async16(uint32_t dst, const void* src) {
    asm volatile("cp.async.ca.shared.global [%0], [%1], 16;" :: "r"(dst), "l"(src) : "memory");
}

__global__ __launch_bounds__(NT, 1)
void lstm_fused_kernel(const float* __restrict__ x,
                       const float* __restrict__ params,
                       const float* __restrict__ W_ih,
                       const float* __restrict__ W_hh,
                       const float* __restrict__ b_ih,
                       const float* __restrict__ b_hh,
                       const float* __restrict__ W_lin,
                       const float* __restrict__ b_lin,
                       float* __restrict__ out,
                       int B)
{
    __shared__ __align__(16) __half ring[NB][32][RH];  // per-batch fp16 h ring  (25088B)
    __shared__ __align__(16) float  psm[NB][32][PP];   // params window          (14336B)
    __shared__ __align__(16) float  xw[NB][32];        // x window               (896B)
    __shared__ __align__(16) float  wlin[68];

    const int tid = threadIdx.x;                       // 0..351
    // slot packing: 350 real slots; slot s -> (batch s/50, unit s%50)
    const int s  = min(tid, NB * HH - 1);
    const int q  = s / HH;                             // CTA-local batch 0..6
    const int u  = s - q * HH;                         // unit 0..49
    const bool real_slot = (tid < NB * HH);
    const int b0cta = blockIdx.x * NB;

    // ---- init ----
    for (int i = tid; i < NB * HH; i += NT)
        ring[i / HH][31][i % HH] = __float2half_rn(0.0f);
    if (tid < 68) wlin[tid] = (tid < HH + PP) ? W_lin[tid] : 0.0f;
    const float blin = b_lin[0];

    // ---- per-thread weights: gates i,f,g,o for (q,u); 0.5 folded into i,f,o ----
    __half2 w[4][25];
    __half2 wx_if, wb_if, wx_go, wb_go;
    {
        float wihv[4], biasv[4];
        #pragma unroll
        for (int k = 0; k < 4; ++k) {
            const int r = k * HH + u;
            const float sc = (k == 2) ? 1.0f : 0.5f;
            wihv[k]  = sc * W_ih[r];
            biasv[k] = sc * (b_ih[r] + b_hh[r]);
            const float2* wr = reinterpret_cast<const float2*>(W_hh + r * HH);
            #pragma unroll
            for (int p = 0; p < 25; ++p) {
                float2 v = wr[p];
                w[k][p] = __floats2half2_rn(sc * v.x, sc * v.y);
            }
        }
        wx_if = __floats2half2_rn(wihv[0], wihv[1]);
        wb_if = __floats2half2_rn(biasv[0], biasv[1]);
        wx_go = __floats2half2_rn(wihv[2], wihv[3]);
        wb_go = __floats2half2_rn(biasv[2], biasv[3]);
    }
    const __half2 H55   = __floats2half2_rn(0.5f, 0.5f);
    const __half2 Hm_go = __floats2half2_rn(1.0f, 0.5f);
    const __half2 Ha_go = __floats2half2_rn(0.0f, 0.5f);
    __syncthreads();

    const __half* ringq = &ring[q][0][0];
    float c = 0.0f;

    #pragma unroll 1
    for (int win = 0; win < TT / 32; ++win) {
        const int t0 = win * 32;

        // ---- window prefetch: params (NB x 32 x 16 floats) + x (NB x 32 floats) ----
        for (int i = tid; i < NB * 128; i += NT) {     // 896 chunks of 16B
            const int bsel = i >> 7;
            const int slot = (i >> 2) & 31;
            const int seg  = i & 3;
            const int bl   = min(b0cta + bsel, B - 1);
            const float* src = params + ((size_t)bl * TT + (t0 + slot)) * PP + seg * 4;
            cp_async16((uint32_t)__cvta_generic_to_shared(&psm[bsel][slot][seg * 4]), src);
        }
        for (int i = tid; i < NB * 8; i += NT) {       // 56 chunks of 16B (x window)
            const int bsel  = i / 8;
            const int chunk = i & 7;
            const int bl    = min(b0cta + bsel, B - 1);
            const float* src = x + (size_t)bl * TT + t0 + chunk * 4;
            cp_async16((uint32_t)__cvta_generic_to_shared(&xw[bsel][chunk * 4]), src);
        }
        asm volatile("cp.async.commit_group;" ::: "memory");
        asm volatile("cp.async.wait_group 0;" ::: "memory");
        __syncthreads();                               // xw visible before first step

        // ---- 32 recurrence steps; no branch tests inside ----
        #pragma unroll 4
        for (int tw = 0; tw < 32; ++tw) {
            const int prev = (tw + 31) & 31;

            // h[t-1]: 6 LDS.128 + 1 LDS.32 broadcast
            const __half* hrow = ringq + prev * RH;
            uint4 hv[6];
            const uint4* rp = reinterpret_cast<const uint4*>(hrow);
            #pragma unroll
            for (int p = 0; p < 6; ++p) hv[p] = rp[p];
            const unsigned htail = reinterpret_cast<const unsigned*>(hrow)[24];

            // 4 gate dots
            __half2 a0[4], a1[4];
            #pragma unroll
            for (int k = 0; k < 4; ++k) { a0[k] = __floats2half2_rn(0.f, 0.f); a1[k] = a0[k]; }
            #pragma unroll
            for (int p = 0; p < 6; ++p) {
                #pragma unroll
                for (int k = 0; k < 4; ++k) {
                    a0[k] = __hfma2(w[k][4 * p + 0], u2h(hv[p].x), a0[k]);
                    a1[k] = __hfma2(w[k][4 * p + 1], u2h(hv[p].y), a1[k]);
                    a0[k] = __hfma2(w[k][4 * p + 2], u2h(hv[p].z), a0[k]);
                    a1[k] = __hfma2(w[k][4 * p + 3], u2h(hv[p].w), a1[k]);
                }
            }
            #pragma unroll
            for (int k = 0; k < 4; ++k) a0[k] = __hfma2(w[k][24], u2h(htail), a0[k]);

            const __half2 si = __hadd2(a0[0], a1[0]);
            const __half2 sf = __hadd2(a0[1], a1[1]);
            const __half2 sg = __hadd2(a0[2], a1[2]);
            const __half2 so = __hadd2(a0[3], a1[3]);

            // packed tail (x converted per step: same __float2half_rn as before)
            const __half2 xx = __half2half2(__float2half_rn(xw[q][tw]));
            const __half2 xg_if = __hfma2(xx, wx_if, wb_if);
            const __half2 xg_go = __hfma2(xx, wx_go, wb_go);
            const __half2 raw_if = __hadd2(
                __hadd2(u2h(prmt(h2u(si), h2u(sf), 0x5410)),
                        u2h(prmt(h2u(si), h2u(sf), 0x7632))), xg_if);
            const __half2 raw_go = __hadd2(
                __hadd2(u2h(prmt(h2u(sg), h2u(so), 0x5410)),
                        u2h(prmt(h2u(sg), h2u(so), 0x7632))), xg_go);

            const __half2 v_if = __hfma2(tanh_h2(raw_if), H55, H55);      // (sig_i, sig_f)
            const __half2 v_go = __hfma2(tanh_h2(raw_go), Hm_go, Ha_go);  // (tanh_g, sig_o)

            const __half2 m = __hmul2(v_if, v_go);     // lo = i*g
            const float ig = __low2float(m);
            const float vf = __high2float(v_if);
            const float vo = __high2float(v_go);

            c = fmaf(vf, c, ig);
            const float h = vo * tanh_hw(c);
            if (real_slot) ring[q][tw][u] = __float2half_rn(h);

            __syncthreads();                           // h[cur] visible
        }

        // ---- window flush: 1 thread per (batch, timestep) ----
        if (tid < NB * 32) {
            const int fb   = tid >> 5;
            const int slot = tid & 31;
            const int tg   = t0 + slot;
            const __half* hr = ring[fb][slot];
            float sacc = blin;
            #pragma unroll
            for (int p = 0; p < 6; ++p) {
                uint4 v = reinterpret_cast<const uint4*>(hr)[p];
                float2 f0 = __half22float2(u2h(v.x));
                float2 f1 = __half22float2(u2h(v.y));
                float2 f2 = __half22float2(u2h(v.z));
                float2 f3 = __half22float2(u2h(v.w));
                sacc = fmaf(f0.x, wlin[8*p+0], sacc); sacc = fmaf(f0.y, wlin[8*p+1], sacc);
                sacc = fmaf(f1.x, wlin[8*p+2], sacc); sacc = fmaf(f1.y, wlin[8*p+3], sacc);
                sacc = fmaf(f2.x, wlin[8*p+4], sacc); sacc = fmaf(f2.y, wlin[8*p+5], sacc);
                sacc = fmaf(f3.x, wlin[8*p+6], sacc); sacc = fmaf(f3.y, wlin[8*p+7], sacc);
            }
            {
                float2 ft = __half22float2(u2h(reinterpret_cast<const unsigned*>(hr)[24]));
                sacc = fmaf(ft.x, wlin[48], sacc); sacc = fmaf(ft.y, wlin[49], sacc);
            }
            const float4* p4 = reinterpret_cast<const float4*>(&psm[fb][slot][0]);
            #pragma unroll
            for (int p = 0; p < 4; ++p) {
                float4 pv = p4[p];
                sacc = fmaf(pv.x, wlin[HH + 4*p + 0], sacc);
                sacc = fmaf(pv.y, wlin[HH + 4*p + 1], sacc);
                sacc = fmaf(pv.z, wlin[HH + 4*p + 2], sacc);
                sacc = fmaf(pv.w, wlin[HH + 4*p + 3], sacc);
            }
            if (b0cta + fb < B)
                out[(size_t)(b0cta + fb) * TT + tg] = sacc;
        }
        __syncthreads();                               // flush done before ring reuse
    }
}

extern "C" void kernel_launch(void* const* d_in, const int* in_sizes, int n_in,
                              void* d_out, int out_size)
{
    const float* x      = (const float*)d_in[0];
    const float* params = (const float*)d_in[1];
    const float* W_ih   = (const float*)d_in[2];
    const float* W_hh   = (const float*)d_in[3];
    const float* b_ih   = (const float*)d_in[4];
    const float* b_hh   = (const float*)d_in[5];
    const float* W_lin  = (const float*)d_in[6];
    const float* b_lin  = (const float*)d_in[7];
    float* out = (float*)d_out;

    const int B = in_sizes[0] / TT;                    // 1024
    const int grid = (B + NB - 1) / NB;                // 147 -> 1 CTA per SM
    lstm_fused_kernel<<<grid, NT>>>(x, params, W_ih, W_hh, b_ih, b_hh,
                                    W_lin, b_lin, out, B);
}